// round 2
// baseline (speedup 1.0000x reference)
#include <cuda_runtime.h>
#include <math.h>

#define BQ    8
#define SEQ   512
#define NVAR  1024
#define TFEAT 7
#define LTOK  1031           // NVAR + TFEAT
#define MTOT  8248           // BQ * LTOK
#define DMOD  128
#define DST   16
#define PREDN 96

// ---------------- scratch (device globals; no allocation allowed) ----------------
__device__ float g_h  [MTOT * DMOD];
__device__ float g_ln1[MTOT * DMOD];
__device__ float g_ffn[MTOT * DMOD];
__device__ float g_xz [MTOT * 512];          // [m][0:128 xr_f |128:256 z_f |256:384 xr_r |384:512 z_r]
__device__ float g_xc [2 * MTOT * DMOD];     // per dir, scan-time order
__device__ float g_dbc[2 * MTOT * 160];      // per dir: delta(128) B(16) C(16), scan-time order
__device__ float g_y  [2 * MTOT * DMOD];     // scan output, ORIGINAL token order
__device__ float g_po [MTOT * PREDN];
__device__ float g_wxp[4 * 160 * DMOD];      // per (l,dir): rows0-127 = dpw@xpw[:8]; 128-159 = xpw[8:40]

// ---------------- combined x_proj/dt_proj weight prep ----------------
__global__ void prep_wd(const float* __restrict__ xpw, const float* __restrict__ dpw,
                        float* __restrict__ out)
{
    int ld = blockIdx.y;                       // 0..3 = l*2+dir
    int idx = blockIdx.x * 256 + threadIdx.x;  // 160*128
    if (idx >= 160 * DMOD) return;
    int i = idx / DMOD, j = idx - i * DMOD;
    const float* xp = xpw + ld * 40 * DMOD;
    float v;
    if (i < DMOD) {
        const float* dp = dpw + (ld * DMOD + i) * 8;
        v = 0.f;
        #pragma unroll
        for (int r = 0; r < 8; r++) v += dp[r] * xp[r * DMOD + j];
    } else {
        v = xp[(8 + (i - DMOD)) * DMOD + j];
    }
    out[ld * 160 * DMOD + idx] = v;
}

// ---------------- generic fp32 GEMM: C[M,N] = A[M,K] @ W[N,K]^T (+epilogue) ------
// EPI: 0 = (+bias if given)   1 = relu(v+bias)   2 = v + (bias?) + resid[m*N+n]
//      3 = xproj: n<128 -> softplus(v + bias[n]); else raw
template<int EPI>
__global__ __launch_bounds__(256) void gemm_k(
    const float* __restrict__ A, const float* __restrict__ W,
    const float* __restrict__ bias, const float* __restrict__ resid,
    float* __restrict__ C, int M, int N, int K)
{
    __shared__ float As[16][64];
    __shared__ float Ws[16][64];
    int bm = blockIdx.y * 64;
    int bn = blockIdx.x * 64;
    int tid = threadIdx.x;
    int tx = tid & 15, ty = tid >> 4;
    int lr = tid >> 2;            // 0..63 tile row for loads
    int lk4 = (tid & 3) * 4;      // 0,4,8,12
    float acc[4][4] = {};

    for (int k0 = 0; k0 < K; k0 += 16) {
        {
            int m = bm + lr;
            float4 v = make_float4(0.f, 0.f, 0.f, 0.f);
            if (m < M) v = *(const float4*)(A + (size_t)m * K + k0 + lk4);
            As[lk4 + 0][lr] = v.x; As[lk4 + 1][lr] = v.y;
            As[lk4 + 2][lr] = v.z; As[lk4 + 3][lr] = v.w;
        }
        {
            int n = bn + lr;
            float4 v = make_float4(0.f, 0.f, 0.f, 0.f);
            if (n < N) v = *(const float4*)(W + (size_t)n * K + k0 + lk4);
            Ws[lk4 + 0][lr] = v.x; Ws[lk4 + 1][lr] = v.y;
            Ws[lk4 + 2][lr] = v.z; Ws[lk4 + 3][lr] = v.w;
        }
        __syncthreads();
        #pragma unroll
        for (int k = 0; k < 16; k++) {
            float4 a4 = *(const float4*)&As[k][ty * 4];
            float4 w4 = *(const float4*)&Ws[k][tx * 4];
            float av[4] = {a4.x, a4.y, a4.z, a4.w};
            float wv[4] = {w4.x, w4.y, w4.z, w4.w};
            #pragma unroll
            for (int i = 0; i < 4; i++)
                #pragma unroll
                for (int j = 0; j < 4; j++)
                    acc[i][j] = fmaf(av[i], wv[j], acc[i][j]);
        }
        __syncthreads();
    }

    #pragma unroll
    for (int i = 0; i < 4; i++) {
        int m = bm + ty * 4 + i;
        if (m >= M) continue;
        #pragma unroll
        for (int j = 0; j < 4; j++) {
            int n = bn + tx * 4 + j;
            if (n >= N) continue;
            float v = acc[i][j];
            if (EPI == 0) {
                if (bias) v += bias[n];
            } else if (EPI == 1) {
                v = fmaxf(v + bias[n], 0.f);
            } else if (EPI == 2) {
                if (bias) v += bias[n];
                v += resid[(size_t)m * N + n];
            } else if (EPI == 3) {
                if (n < DMOD) {
                    v += bias[n];
                    v = (v > 20.f) ? v : log1pf(__expf(v));
                }
            }
            C[(size_t)m * N + n] = v;
        }
    }
}

// ---------------- embedding GEMM: h = tokens @ emb_w^T + b ----------------
__global__ __launch_bounds__(256) void emb_gemm(
    const float* __restrict__ x_enc, const float* __restrict__ x_mark,
    const float* __restrict__ W, const float* __restrict__ bias,
    float* __restrict__ C)
{
    __shared__ float As[16][64];
    __shared__ float Ws[16][64];
    int bm = blockIdx.y * 64;
    int bn = blockIdx.x * 64;
    int tid = threadIdx.x;
    int tx = tid & 15, ty = tid >> 4;
    float acc[4][4] = {};

    int ai = tid & 63;            // tile row (token) — consecutive threads -> consecutive v
    int akq = tid >> 6;           // 0..3
    int m = bm + ai;
    int bb = m / LTOK;
    int v = m - bb * LTOK;
    bool mvalid = (m < MTOT);

    int wr = tid >> 2;
    int wk4 = (tid & 3) * 4;

    for (int k0 = 0; k0 < SEQ; k0 += 16) {
        #pragma unroll
        for (int u = 0; u < 4; u++) {
            int kk = akq * 4 + u;
            int s = k0 + kk;
            float val = 0.f;
            if (mvalid) {
                if (v < NVAR) {
                    float x = x_enc[((size_t)bb * SEQ + s) * NVAR + v];
                    val = (x == -9999.0f) ? -1.0f : x;
                } else {
                    val = x_mark[((size_t)bb * SEQ + s) * TFEAT + (v - NVAR)];
                }
            }
            As[kk][ai] = val;
        }
        {
            int n = bn + wr;                       // N = 128 always valid
            float4 w4 = *(const float4*)(W + (size_t)n * SEQ + k0 + wk4);
            Ws[wk4 + 0][wr] = w4.x; Ws[wk4 + 1][wr] = w4.y;
            Ws[wk4 + 2][wr] = w4.z; Ws[wk4 + 3][wr] = w4.w;
        }
        __syncthreads();
        #pragma unroll
        for (int k = 0; k < 16; k++) {
            float4 a4 = *(const float4*)&As[k][ty * 4];
            float4 w4 = *(const float4*)&Ws[k][tx * 4];
            float av[4] = {a4.x, a4.y, a4.z, a4.w};
            float wv[4] = {w4.x, w4.y, w4.z, w4.w};
            #pragma unroll
            for (int i = 0; i < 4; i++)
                #pragma unroll
                for (int j = 0; j < 4; j++)
                    acc[i][j] = fmaf(av[i], wv[j], acc[i][j]);
        }
        __syncthreads();
    }
    #pragma unroll
    for (int i = 0; i < 4; i++) {
        int mm = bm + ty * 4 + i;
        if (mm >= MTOT) continue;
        #pragma unroll
        for (int j = 0; j < 4; j++) {
            int nn = bn + tx * 4 + j;
            C[(size_t)mm * DMOD + nn] = acc[i][j] + bias[nn];
        }
    }
}

// ---------------- depthwise causal conv (DCONV=2) + silu, scan-time order --------
__global__ void conv_silu(const float* __restrict__ xz, const float* __restrict__ cw,
                          const float* __restrict__ cb, float* __restrict__ xc, int l)
{
    int idx = blockIdx.x * 256 + threadIdx.x;
    if (idx >= 2 * MTOT * DMOD) return;
    int dir = idx / (MTOT * DMOD);
    int rem = idx - dir * (MTOT * DMOD);
    int row = rem >> 7;              // b*LTOK + tau
    int d = rem & (DMOD - 1);
    int b = row / LTOK;
    int tau = row - b * LTOK;
    int t = dir ? (LTOK - 1 - tau) : tau;
    int ld = l * 2 + dir;
    float c0 = cw[(ld * DMOD + d) * 2 + 0];
    float c1 = cw[(ld * DMOD + d) * 2 + 1];
    float x1 = xz[((size_t)(b * LTOK + t)) * 512 + dir * 256 + d];
    float acc = x1 * c1 + cb[ld * DMOD + d];
    if (tau > 0) {
        int tp = dir ? (t + 1) : (t - 1);
        acc += xz[((size_t)(b * LTOK + tp)) * 512 + dir * 256 + d] * c0;
    }
    acc = acc / (1.f + __expf(-acc)) * 1.f;     // silu: x*sigmoid(x)
    // note: silu(x) = x * sigmoid(x); above computes x/(1+e^-x) which equals it
    xc[(size_t)dir * MTOT * DMOD + rem] = acc;
}

// ---------------- selective scan ----------------
__global__ __launch_bounds__(256) void scan_k(
    const float* __restrict__ dbc, const float* __restrict__ xc,
    const float* __restrict__ xz, const float* __restrict__ A_log,
    const float* __restrict__ Dpar, float* __restrict__ y, int l)
{
    int n  = threadIdx.x & 15;
    int dl = threadIdx.x >> 4;
    int d  = blockIdx.x * 16 + dl;
    int b  = blockIdx.y;
    int dir = blockIdx.z;
    int ld = l * 2 + dir;

    float a  = -__expf(A_log[(ld * DMOD + d) * DST + n]);
    float Dp = Dpar[ld * DMOD + d];

    const float* dbcp = dbc + (size_t)dir * MTOT * 160 + (size_t)b * LTOK * 160;
    const float* xcp  = xc  + (size_t)dir * MTOT * DMOD + (size_t)b * LTOK * DMOD;
    const float* zp   = xz  + (size_t)b * LTOK * 512 + 128 + dir * 256;
    float*       yp   = y   + (size_t)dir * MTOT * DMOD + (size_t)b * LTOK * DMOD;

    float hst = 0.f;
    #pragma unroll 2
    for (int tau = 0; tau < LTOK; tau++) {
        const float* row = dbcp + (size_t)tau * 160;
        float delta = row[d];
        float Bv    = row[128 + n];
        float Cv    = row[144 + n];
        float xcv   = xcp[(size_t)tau * DMOD + d];
        float dA = __expf(delta * a);
        hst = fmaf(dA, hst, delta * Bv * xcv);
        float p = hst * Cv;
        p += __shfl_xor_sync(0xffffffffu, p, 8);
        p += __shfl_xor_sync(0xffffffffu, p, 4);
        p += __shfl_xor_sync(0xffffffffu, p, 2);
        p += __shfl_xor_sync(0xffffffffu, p, 1);
        if (n == 0) {
            int t = dir ? (LTOK - 1 - tau) : tau;
            float z = zp[(size_t)t * 512 + d];
            float sz = z / (1.f + __expf(-z));
            yp[(size_t)t * DMOD + d] = (p + Dp * xcv) * sz;
        }
    }
}

// ---------------- layernorm over last dim (128) ----------------
__global__ void ln_k(const float* __restrict__ in, float* __restrict__ out,
                     const float* __restrict__ w, const float* __restrict__ b)
{
    int row = blockIdx.x;
    int t = threadIdx.x;
    float v = in[(size_t)row * DMOD + t];
    __shared__ float sm[4], sm2[4];
    float s = v;
    #pragma unroll
    for (int o = 16; o; o >>= 1) s += __shfl_xor_sync(0xffffffffu, s, o);
    if ((t & 31) == 0) sm[t >> 5] = s;
    __syncthreads();
    float mu = (sm[0] + sm[1] + sm[2] + sm[3]) * (1.f / 128.f);
    float dv = v - mu;
    float q = dv * dv;
    #pragma unroll
    for (int o = 16; o; o >>= 1) q += __shfl_xor_sync(0xffffffffu, q, o);
    if ((t & 31) == 0) sm2[t >> 5] = q;
    __syncthreads();
    float var = (sm2[0] + sm2[1] + sm2[2] + sm2[3]) * (1.f / 128.f);
    out[(size_t)row * DMOD + t] = dv * rsqrtf(var + 1e-5f) * w[t] + b[t];
}

// ---------------- final transposed write ----------------
__global__ void write_out(const float* __restrict__ P, float* __restrict__ out)
{
    int idx = blockIdx.x * 256 + threadIdx.x;
    if (idx >= BQ * PREDN * NVAR) return;
    int v = idx & (NVAR - 1);
    int p = (idx >> 10) % PREDN;
    int b = idx / (PREDN * NVAR);
    out[idx] = P[((size_t)(b * LTOK + v)) * PREDN + p];
}

// ---------------- launcher ----------------
extern "C" void kernel_launch(void* const* d_in, const int* in_sizes, int n_in,
                              void* d_out, int out_size)
{
    const float* x_enc     = (const float*)d_in[0];
    const float* x_mark    = (const float*)d_in[1];
    const float* emb_w     = (const float*)d_in[4];
    const float* emb_b     = (const float*)d_in[5];
    const float* in_proj_w = (const float*)d_in[6];
    const float* conv_w    = (const float*)d_in[7];
    const float* conv_b    = (const float*)d_in[8];
    const float* x_proj_w  = (const float*)d_in[9];
    const float* dt_proj_w = (const float*)d_in[10];
    const float* dt_proj_b = (const float*)d_in[11];
    const float* A_log     = (const float*)d_in[12];
    const float* D_param   = (const float*)d_in[13];
    const float* out_projw = (const float*)d_in[14];
    const float* norm1_w   = (const float*)d_in[15];
    const float* norm1_b   = (const float*)d_in[16];
    const float* norm2_w   = (const float*)d_in[17];
    const float* norm2_b   = (const float*)d_in[18];
    const float* ffn_w1    = (const float*)d_in[19];
    const float* ffn_b1    = (const float*)d_in[20];
    const float* ffn_w2    = (const float*)d_in[21];
    const float* ffn_b2    = (const float*)d_in[22];
    const float* fnorm_w   = (const float*)d_in[23];
    const float* fnorm_b   = (const float*)d_in[24];
    const float* proj_w    = (const float*)d_in[25];
    const float* proj_b    = (const float*)d_in[26];

    float *ph, *pln1, *pffn, *pxz, *pxc, *pdbc, *py, *ppo, *pwxp;
    cudaGetSymbolAddress((void**)&ph,   g_h);
    cudaGetSymbolAddress((void**)&pln1, g_ln1);
    cudaGetSymbolAddress((void**)&pffn, g_ffn);
    cudaGetSymbolAddress((void**)&pxz,  g_xz);
    cudaGetSymbolAddress((void**)&pxc,  g_xc);
    cudaGetSymbolAddress((void**)&pdbc, g_dbc);
    cudaGetSymbolAddress((void**)&py,   g_y);
    cudaGetSymbolAddress((void**)&ppo,  g_po);
    cudaGetSymbolAddress((void**)&pwxp, g_wxp);

    const int MT = (MTOT + 63) / 64;   // 129

    prep_wd<<<dim3(80, 4), 256>>>(x_proj_w, dt_proj_w, pwxp);
    emb_gemm<<<dim3(2, MT), 256>>>(x_enc, x_mark, emb_w, emb_b, ph);

    for (int l = 0; l < 2; l++) {
        // in_proj both directions at once: h(M,128) @ W(512,128)^T
        gemm_k<0><<<dim3(8, MT), 256>>>(ph, in_proj_w + l * 2 * 256 * DMOD,
                                        nullptr, nullptr, pxz, MTOT, 512, DMOD);
        conv_silu<<<(2 * MTOT * DMOD + 255) / 256, 256>>>(pxz, conv_w, conv_b, pxc, l);
        for (int dir = 0; dir < 2; dir++) {
            int ld = l * 2 + dir;
            gemm_k<3><<<dim3(3, MT), 256>>>(pxc + (size_t)dir * MTOT * DMOD,
                                            pwxp + (size_t)ld * 160 * DMOD,
                                            dt_proj_b + ld * DMOD, nullptr,
                                            pdbc + (size_t)dir * MTOT * 160,
                                            MTOT, 160, DMOD);
        }
        scan_k<<<dim3(8, 8, 2), 256>>>(pdbc, pxc, pxz, A_log, D_param, py, l);
        // out_proj + residual accumulation (two chained accumulating GEMMs)
        gemm_k<2><<<dim3(2, MT), 256>>>(py, out_projw + (size_t)(l * 2 + 0) * DMOD * DMOD,
                                        nullptr, ph, pln1, MTOT, DMOD, DMOD);
        gemm_k<2><<<dim3(2, MT), 256>>>(py + (size_t)MTOT * DMOD,
                                        out_projw + (size_t)(l * 2 + 1) * DMOD * DMOD,
                                        nullptr, pln1, ph, MTOT, DMOD, DMOD);
        ln_k<<<MTOT, 128>>>(ph, pln1, norm1_w + l * DMOD, norm1_b + l * DMOD);
        gemm_k<1><<<dim3(2, MT), 256>>>(pln1, ffn_w1 + (size_t)l * DMOD * DMOD,
                                        ffn_b1 + l * DMOD, nullptr, pffn, MTOT, DMOD, DMOD);
        gemm_k<2><<<dim3(2, MT), 256>>>(pffn, ffn_w2 + (size_t)l * DMOD * DMOD,
                                        ffn_b2 + l * DMOD, pln1, ph, MTOT, DMOD, DMOD);
        ln_k<<<MTOT, 128>>>(ph, ph, norm2_w + l * DMOD, norm2_b + l * DMOD);
    }

    ln_k<<<MTOT, 128>>>(ph, pln1, fnorm_w, fnorm_b);
    gemm_k<0><<<dim3(2, MT), 256>>>(pln1, proj_w, proj_b, nullptr, ppo, MTOT, PREDN, DMOD);
    write_out<<<(BQ * PREDN * NVAR + 255) / 256, 256>>>(ppo, (float*)d_out);
}